// round 3
// baseline (speedup 1.0000x reference)
#include <cuda_runtime.h>
#include <cstdint>

// Problem constants (from reference):
//   x: [B=64, E=2048] int32, values in [1, 2047]
//   Y: [J=2048, E=2048, B=64] float32
//   Y[j,e,b] = ((2*x[b,j]+1) >> min(E-1-e, 31)) & 1
// v = 2*x+1 <= 4095 < 2^12  =>  bit is 0 for all shifts >= 12,
// i.e. zero for every e < E-13 = 2035. Only the last 13 e-columns
// per j can be nonzero (~0.64% of the 1.07 GB output).

constexpr int E_DIM = 2048;
constexpr int B_DIM = 64;
constexpr unsigned NONZERO_E_START = E_DIM - 13;  // 2035

// Total float4 elements: J * E * B / 4 = 2048 * 2048 * 16 = 67,108,864
constexpr unsigned TOTAL_F4 = (unsigned)E_DIM * (unsigned)E_DIM * (B_DIM / 4);
constexpr unsigned HALF_F4  = TOTAL_F4 / 2;

__device__ __forceinline__ float4 compute_f4(const int* __restrict__ x,
                                             unsigned idx4) {
    // Each (j,e) pair owns B=64 consecutive floats = 16 float4s.
    unsigned pair = idx4 >> 4;            // j * E + e
    unsigned e    = pair & (E_DIM - 1);   // E is a power of two

    float4 val = make_float4(0.f, 0.f, 0.f, 0.f);
    if (e >= NONZERO_E_START) {
        unsigned j = pair >> 11;          // pair / E
        unsigned b = (idx4 & 15u) << 2;   // first of 4 batch lanes
        int shift = (E_DIM - 1) - (int)e; // in [0, 12]
        // x layout: [B, E] row-major -> x[b*E + j]
        int v0 = 2 * __ldg(&x[(b + 0) * E_DIM + j]) + 1;
        int v1 = 2 * __ldg(&x[(b + 1) * E_DIM + j]) + 1;
        int v2 = 2 * __ldg(&x[(b + 2) * E_DIM + j]) + 1;
        int v3 = 2 * __ldg(&x[(b + 3) * E_DIM + j]) + 1;
        val.x = (float)((v0 >> shift) & 1);
        val.y = (float)((v1 >> shift) & 1);
        val.z = (float)((v2 >> shift) & 1);
        val.w = (float)((v3 >> shift) & 1);
    }
    return val;
}

__global__ void embedding_bits_kernel(const int* __restrict__ x,
                                      float4* __restrict__ out) {
    unsigned idx4 = blockIdx.x * blockDim.x + threadIdx.x;  // < HALF_F4
    // Two independent STG.128 per thread (MLP=2), both fully coalesced.
    float4 a = compute_f4(x, idx4);
    float4 b = compute_f4(x, idx4 + HALF_F4);
    out[idx4] = a;
    out[idx4 + HALF_F4] = b;
}

extern "C" void kernel_launch(void* const* d_in, const int* in_sizes, int n_in,
                              void* d_out, int out_size) {
    const int* x = (const int*)d_in[0];
    float4* out = (float4*)d_out;

    constexpr int THREADS = 256;
    constexpr unsigned BLOCKS = HALF_F4 / THREADS;  // 131,072 (exact)
    embedding_bits_kernel<<<BLOCKS, THREADS>>>(x, out);
}

// round 4
// speedup vs baseline: 1.0020x; 1.0020x over previous
#include <cuda_runtime.h>
#include <cstdint>

// Problem constants (from reference):
//   x: [B=64, E=2048] int32, values in [1, 2047]
//   Y: [J=2048, E=2048, B=64] float32
//   Y[j,e,b] = ((2*x[b,j]+1) >> min(E-1-e, 31)) & 1
// v = 2*x+1 <= 4095 < 2^12  =>  bit is 0 for all shifts >= 12,
// i.e. zero for every e < E-13 = 2035. Only the last 13 e-columns
// per j can be nonzero (~0.64% of the 1.07 GB output).
//
// R3 bench: 145.8us, DRAM=89.3%, 7078 GB/s. Store-bound at the HBM
// write roofline. This round: streaming stores (.cs, evict-first —
// output has zero reuse, don't churn L2) + 4 float4s per thread.

constexpr int E_DIM = 2048;
constexpr unsigned NONZERO_E_START = E_DIM - 13;  // 2035

// Total float4 elements: J * E * B / 4 = 2048 * 2048 * 16 = 67,108,864
constexpr unsigned TOTAL_F4 = (unsigned)E_DIM * (unsigned)E_DIM * 16u;
constexpr unsigned QUARTER_F4 = TOTAL_F4 / 4;     // 16,777,216

__device__ __forceinline__ float4 compute_f4(const int* __restrict__ x,
                                             unsigned idx4) {
    // Each (j,e) pair owns B=64 consecutive floats = 16 float4s.
    unsigned pair = idx4 >> 4;            // j * E + e
    unsigned e    = pair & (E_DIM - 1);   // E is a power of two

    float4 val = make_float4(0.f, 0.f, 0.f, 0.f);
    if (e >= NONZERO_E_START) {
        unsigned j = pair >> 11;          // pair / E
        unsigned b = (idx4 & 15u) << 2;   // first of 4 batch lanes
        int shift = (E_DIM - 1) - (int)e; // in [0, 12]
        // x layout: [B, E] row-major -> x[b*E + j]
        int v0 = 2 * __ldg(&x[(b + 0) * E_DIM + j]) + 1;
        int v1 = 2 * __ldg(&x[(b + 1) * E_DIM + j]) + 1;
        int v2 = 2 * __ldg(&x[(b + 2) * E_DIM + j]) + 1;
        int v3 = 2 * __ldg(&x[(b + 3) * E_DIM + j]) + 1;
        val.x = (float)((v0 >> shift) & 1);
        val.y = (float)((v1 >> shift) & 1);
        val.z = (float)((v2 >> shift) & 1);
        val.w = (float)((v3 >> shift) & 1);
    }
    return val;
}

// Streaming store: evict-first, output is dead-on-write (no reuse).
__device__ __forceinline__ void stg_cs_f4(float4* p, float4 v) {
    asm volatile("st.global.cs.v4.f32 [%0], {%1, %2, %3, %4};"
                 :: "l"(p), "f"(v.x), "f"(v.y), "f"(v.z), "f"(v.w)
                 : "memory");
}

__global__ void embedding_bits_kernel(const int* __restrict__ x,
                                      float4* __restrict__ out) {
    unsigned idx4 = blockIdx.x * blockDim.x + threadIdx.x;  // < QUARTER_F4
    // Four independent STG.128.CS per thread, all fully coalesced
    // (consecutive lanes -> consecutive 16B, 512B per warp per store).
    float4 a = compute_f4(x, idx4);
    float4 b = compute_f4(x, idx4 + QUARTER_F4);
    float4 c = compute_f4(x, idx4 + 2 * QUARTER_F4);
    float4 d = compute_f4(x, idx4 + 3 * QUARTER_F4);
    stg_cs_f4(&out[idx4], a);
    stg_cs_f4(&out[idx4 + QUARTER_F4], b);
    stg_cs_f4(&out[idx4 + 2 * QUARTER_F4], c);
    stg_cs_f4(&out[idx4 + 3 * QUARTER_F4], d);
}

extern "C" void kernel_launch(void* const* d_in, const int* in_sizes, int n_in,
                              void* d_out, int out_size) {
    const int* x = (const int*)d_in[0];
    float4* out = (float4*)d_out;

    constexpr int THREADS = 256;
    constexpr unsigned BLOCKS = QUARTER_F4 / THREADS;  // 65,536 (exact)
    embedding_bits_kernel<<<BLOCKS, THREADS>>>(x, out);
}